// round 7
// baseline (speedup 1.0000x reference)
#include <cuda_runtime.h>
#include <math.h>
#include <stdint.h>

#define KNN 32
#define VOCAB 32000
#define TOKENS 2048           // B*S = 4*512
#define NTHREADS 256
#define ROW_BYTES 128000      // 32000 floats
#define CH_FLOATS 3200
#define CH_F4     800         // float4 per chunk
#define CH_BYTES  12800
#define NCH       10          // chunks per row
#define NBUF      3

typedef unsigned long long u64;

__device__ __forceinline__ uint32_t smem_u32(const void* p) {
    uint32_t a;
    asm("{ .reg .u64 t; cvta.to.shared.u64 t, %1; cvt.u32.u64 %0, t; }" : "=r"(a) : "l"(p));
    return a;
}
__device__ __forceinline__ void mbar_init(uint32_t a, uint32_t cnt) {
    asm volatile("mbarrier.init.shared.b64 [%0], %1;" :: "r"(a), "r"(cnt) : "memory");
}
__device__ __forceinline__ void mbar_expect_tx(uint32_t a, uint32_t bytes) {
    asm volatile("mbarrier.arrive.expect_tx.shared.b64 _, [%0], %1;" :: "r"(a), "r"(bytes) : "memory");
}
__device__ __forceinline__ void mbar_wait(uint32_t a, uint32_t parity) {
    asm volatile(
        "{\n\t.reg .pred P;\n"
        "W%=:\n\t"
        "mbarrier.try_wait.parity.acquire.cta.shared::cta.b64 P, [%0], %1, 0x989680;\n\t"
        "@P bra D%=;\n\t"
        "bra W%=;\n"
        "D%=:\n\t}"
        :: "r"(a), "r"(parity) : "memory");
}
__device__ __forceinline__ void bulk_g2s(uint32_t dst_smem, const void* src, uint32_t bytes, uint32_t mbar) {
    asm volatile(
        "cp.async.bulk.shared::cluster.global.mbarrier::complete_tx::bytes [%0], [%1], %2, [%3];"
        :: "r"(dst_smem), "l"(src), "r"(bytes), "r"(mbar) : "memory");
}
__device__ __forceinline__ void fence_proxy_async_cta() {
    asm volatile("fence.proxy.async.shared::cta;" ::: "memory");
}

__device__ __forceinline__ float warp_sum(float v) {
    #pragma unroll
    for (int o = 16; o > 0; o >>= 1) v += __shfl_xor_sync(0xffffffffu, v, o);
    return v;
}
__device__ __forceinline__ float warp_max(float v) {
    #pragma unroll
    for (int o = 16; o > 0; o >>= 1) v = fmaxf(v, __shfl_xor_sync(0xffffffffu, v, o));
    return v;
}

// Lock-free sorted top-8 insert: cascading atomicMax. Displaced keys push down.
__device__ __forceinline__ void cascade_insert(u64* slots, u64 key) {
    #pragma unroll
    for (int s = 0; s < 8; s++) {
        u64 old = atomicMax(&slots[s], key);
        if (old < key) key = old;
        if (key == 0ull) break;
    }
}

// Rare path: push qualifying elements of one float4 into the shared top-8.
__device__ __noinline__ void push4(float4 v, float e8f, u64* slots,
                                   unsigned tid, unsigned* cnt) {
    float e[4] = {v.x, v.y, v.z, v.w};
    #pragma unroll
    for (int j = 0; j < 4; j++) {
        if (e[j] >= e8f) {
            u64 key = (((u64)__float_as_uint(e[j])) << 32)
                    | (u64)((tid << 16) | ((*cnt)++ & 0xffffu));
            if (key > ((volatile u64*)slots)[7]) cascade_insert(slots, key);
        }
    }
}

__global__ __launch_bounds__(NTHREADS) void robust_combiner_kernel(
    const int*   __restrict__ tgt_index,
    const float* __restrict__ knn_dists,
    const float* __restrict__ knn_key,
    const float* __restrict__ net_probs,
    const float* __restrict__ net_sel,
    const float* __restrict__ W_func, const float* __restrict__ b_func,
    const float* __restrict__ W1a,    const float* __restrict__ b1a,
    const float* __restrict__ W1b,    const float* __restrict__ b1b,
    const float* __restrict__ W2a,    const float* __restrict__ b2a,
    const float* __restrict__ W2b,    const float* __restrict__ b2b,
    float* __restrict__ out)
{
    const int t   = blockIdx.x;
    const int tid = threadIdx.x;

    __shared__ float4 s_buf[NBUF][CH_F4];          // 38400 B
    __shared__ float  s_W2a[32 * 64];              // 8192 B
    __shared__ u64    s_mbar[NBUF];
    __shared__ u64    s_seed[8];
    __shared__ u64    s_slots[8];
    __shared__ float  s_topv[8];
    __shared__ float  s_d[KNN], s_cnt[KNN], s_p[KNN];
    __shared__ int    s_tgt[KNN];

    #pragma unroll
    for (int j = 0; j < 8; j++) s_W2a[tid * 8 + j] = W2a[tid * 8 + j];
    if (tid < 8) { s_seed[tid] = 0ull; s_slots[tid] = 0ull; }

    uint32_t mb[NBUF];
    #pragma unroll
    for (int b = 0; b < NBUF; b++) mb[b] = smem_u32(&s_mbar[b]);
    uint32_t bufa[NBUF];
    #pragma unroll
    for (int b = 0; b < NBUF; b++) bufa[b] = smem_u32(&s_buf[b][0]);

    const char* srow = (const char*)net_probs + (size_t)t * ROW_BYTES;
    float* orow = out + (size_t)t * VOCAB;

    if (tid == 0) {
        #pragma unroll
        for (int b = 0; b < NBUF; b++) mbar_init(mb[b], 1);
    }
    __syncthreads();
    if (tid == 0) {
        fence_proxy_async_cta();
        #pragma unroll
        for (int b = 0; b < NBUF; b++) {
            mbar_expect_tx(mb[b], CH_BYTES);
            bulk_g2s(bufa[b], srow + b * CH_BYTES, CH_BYTES, mb[b]);
        }
    }

    // -------- Seed threshold from chunk 0: 8th largest of 256 per-thread maxes --------
    mbar_wait(mb[0], 0);
    float m = 0.0f;
    #pragma unroll
    for (int j = 0; j < 4; j++) {
        int i = j * NTHREADS + tid;
        if (i < CH_F4) {
            float4 v = s_buf[0][i];
            m = fmaxf(m, fmaxf(fmaxf(v.x, v.y), fmaxf(v.z, v.w)));
        }
    }
    {
        float cand = m;
        #pragma unroll
        for (int r = 0; r < 8; r++) {
            u64 key = (((u64)__float_as_uint(cand)) << 32) | (unsigned)tid;
            atomicMax(&s_seed[r], key);
            __syncthreads();
            if ((unsigned)(s_seed[r] & 0xffffffffull) == (unsigned)tid) cand = 0.0f;
        }
    }
    const float e8f = __uint_as_float((unsigned)(s_seed[7] >> 32));
    unsigned pcnt = 0;

#define PROC4(v) do {                                                    \
        float _m = fmaxf(fmaxf((v).x, (v).y), fmaxf((v).z, (v).w));     \
        if (_m >= e8f) push4((v), e8f, s_slots, (unsigned)tid, &pcnt);   \
    } while (0)

    // -------- Main pipelined loop over 10 chunks, 3-deep TMA ring (pure read) --------
    #pragma unroll 1
    for (int c = 0; c < NCH; c++) {
        const int b = c % NBUF;
        if (c > 0) mbar_wait(mb[b], (c / NBUF) & 1);
        #pragma unroll
        for (int j = 0; j < 4; j++) {
            int i = j * NTHREADS + tid;
            if (i < CH_F4) {
                float4 v = s_buf[b][i];
                PROC4(v);
            }
        }
        __syncthreads();
        if (tid == 0 && c + NBUF < NCH) {
            mbar_expect_tx(mb[b], CH_BYTES);
            bulk_g2s(bufa[b], srow + (size_t)(c + NBUF) * CH_BYTES, CH_BYTES, mb[b]);
        }
    }
#undef PROC4
    __syncthreads();

    // -------- Finalize sorted top-8 values --------
    if (tid == 0) {
        float tv[8];
        #pragma unroll
        for (int r = 0; r < 8; r++) tv[r] = __uint_as_float((unsigned)(s_slots[r] >> 32));
        #pragma unroll
        for (int i = 1; i < 8; i++) {
            float x = tv[i]; int j = i - 1;
            while (j >= 0 && tv[j] < x) { tv[j + 1] = tv[j]; j--; }
            tv[j + 1] = x;
        }
        #pragma unroll
        for (int r = 0; r < 8; r++) s_topv[r] = tv[r];
    }
    __syncthreads();

    // -------- Scalar math on warp 0 --------
    if (tid < KNN) {
        const int k = tid;
        const int base = t * KNN;
        const int   tg = tgt_index[base + k];
        const float d  = knn_dists[base + k];
        const float lk = logf(knn_key[base + k]);
        const float ls = logf(net_sel[base + k]);
        s_tgt[k] = tg;
        s_d[k]   = d;
        __syncwarp();

        // distinct-nonzero-label prefix counts
        int flag = (tg != 0) ? 1 : 0;
        for (int j = 0; j < k; j++)
            if (s_tgt[j] == tg) flag = 0;
        int c = flag;
        #pragma unroll
        for (int o = 1; o < 32; o <<= 1) {
            int v = __shfl_up_sync(0xffffffffu, c, o);
            if (k >= o) c += v;
        }
        s_cnt[k] = (float)c;
        __syncwarp();

        // noise_logit: Linear(2,4)-tanh-Linear(4,1)
        float noise = b1b[0];
        #pragma unroll
        for (int mm = 0; mm < 4; mm++) {
            float h = tanhf(W1a[2 * mm] * lk + W1a[2 * mm + 1] * ls + b1a[mm]);
            noise += W1b[mm] * h;
        }

        // sim_lambda: dot([log(top8), log_key, log_sel], W_func) + b
        float part = lk * W_func[8 + k] + ls * W_func[40 + k];
        if (k < 8) part += logf(s_topv[k]) * W_func[k];
        float sim = warp_sum(part) + b_func[0];

        // lambda_logit: Linear(64,32)-tanh-Linear(32,2); lane k = hidden unit k
        float acc = b2a[k];
        #pragma unroll 8
        for (int j = 0; j < 32; j++)
            acc += s_W2a[k * 64 + j] * s_d[j] + s_W2a[k * 64 + 32 + j] * s_cnt[j];
        float h2 = tanhf(acc);
        float l0 = warp_sum(W2b[k]      * h2) + b2b[0];
        float l1 = warp_sum(W2b[32 + k] * h2) + b2b[1];

        float lam   = 1.0f / (1.0f + expf(sim - l0));   // softmax([l0,sim])[0]
        float tempe = 1.0f / (1.0f + expf(-l1));

        // probs = softmax(-d * tempe + noise) over K
        float logit = -d * tempe + noise;
        float mx = warp_max(logit);
        float e  = expf(logit - mx);
        float ssum = warp_sum(e);
        s_p[k] = e / ssum;
        __syncwarp();

        // scatter (sequential, last-wins) into pre-zeroed rows + lambda
        if (k == 0) {
            #pragma unroll
            for (int j = 0; j < KNN; j++) orow[s_tgt[j]] = s_p[j];
            out[(size_t)TOKENS * VOCAB + t] = lam;
        }
    }
}

extern "C" void kernel_launch(void* const* d_in, const int* in_sizes, int n_in,
                              void* d_out, int out_size) {
    const int*   tgt_index = (const int*)  d_in[0];
    const float* knn_dists = (const float*)d_in[1];
    const float* knn_key   = (const float*)d_in[2];
    const float* net_probs = (const float*)d_in[3];
    const float* net_sel   = (const float*)d_in[4];
    const float* W_func    = (const float*)d_in[5];
    const float* b_func    = (const float*)d_in[6];
    const float* W1a       = (const float*)d_in[7];
    const float* b1a       = (const float*)d_in[8];
    const float* W1b       = (const float*)d_in[9];
    const float* b1b       = (const float*)d_in[10];
    const float* W2a       = (const float*)d_in[11];
    const float* b2a       = (const float*)d_in[12];
    const float* W2b       = (const float*)d_in[13];
    const float* b2b       = (const float*)d_in[14];
    float* out = (float*)d_out;

    // Node 1: pure-write zero fill (unidirectional, ~6 TB/s measured in R4).
    cudaMemsetAsync(out, 0, (size_t)out_size * sizeof(float), 0);

    // Node 2: pure-read TMA-ring kernel; scatters 32 values/row into zeroed rows.
    robust_combiner_kernel<<<TOKENS, NTHREADS>>>(
        tgt_index, knn_dists, knn_key, net_probs, net_sel,
        W_func, b_func, W1a, b1a, W1b, b1b, W2a, b2a, W2b, b2b, out);
}

// round 8
// speedup vs baseline: 1.0477x; 1.0477x over previous
#include <cuda_runtime.h>
#include <math.h>
#include <stdint.h>

#define KNN 32
#define VOCAB 32000
#define TOKENS 2048           // B*S = 4*512
#define NTHREADS 256
#define ROW_BYTES 128000      // 32000 floats
#define CH_FLOATS 3200
#define CH_F4     800         // float4 per chunk
#define CH_BYTES  12800
#define NCH_ROW   10          // chunks per row
#define ROWS_PER_CTA 4
#define NCH_CTA   (NCH_ROW * ROWS_PER_CTA)   // 40
#define NBLOCKS   (TOKENS / ROWS_PER_CTA)    // 512
#define NBUF      3

typedef unsigned long long u64;

__device__ __forceinline__ uint32_t smem_u32(const void* p) {
    uint32_t a;
    asm("{ .reg .u64 t; cvta.to.shared.u64 t, %1; cvt.u32.u64 %0, t; }" : "=r"(a) : "l"(p));
    return a;
}
__device__ __forceinline__ void mbar_init(uint32_t a, uint32_t cnt) {
    asm volatile("mbarrier.init.shared.b64 [%0], %1;" :: "r"(a), "r"(cnt) : "memory");
}
__device__ __forceinline__ void mbar_expect_tx(uint32_t a, uint32_t bytes) {
    asm volatile("mbarrier.arrive.expect_tx.shared.b64 _, [%0], %1;" :: "r"(a), "r"(bytes) : "memory");
}
__device__ __forceinline__ void mbar_wait(uint32_t a, uint32_t parity) {
    asm volatile(
        "{\n\t.reg .pred P;\n"
        "W%=:\n\t"
        "mbarrier.try_wait.parity.acquire.cta.shared::cta.b64 P, [%0], %1, 0x989680;\n\t"
        "@P bra D%=;\n\t"
        "bra W%=;\n"
        "D%=:\n\t}"
        :: "r"(a), "r"(parity) : "memory");
}
__device__ __forceinline__ void bulk_g2s(uint32_t dst_smem, const void* src, uint32_t bytes, uint32_t mbar) {
    asm volatile(
        "cp.async.bulk.shared::cluster.global.mbarrier::complete_tx::bytes [%0], [%1], %2, [%3];"
        :: "r"(dst_smem), "l"(src), "r"(bytes), "r"(mbar) : "memory");
}
__device__ __forceinline__ void fence_proxy_async_cta() {
    asm volatile("fence.proxy.async.shared::cta;" ::: "memory");
}

__device__ __forceinline__ float warp_sum(float v) {
    #pragma unroll
    for (int o = 16; o > 0; o >>= 1) v += __shfl_xor_sync(0xffffffffu, v, o);
    return v;
}
__device__ __forceinline__ float warp_max(float v) {
    #pragma unroll
    for (int o = 16; o > 0; o >>= 1) v = fmaxf(v, __shfl_xor_sync(0xffffffffu, v, o));
    return v;
}

// Lock-free sorted top-8 insert: cascading atomicMax. Displaced keys push down.
__device__ __forceinline__ void cascade_insert(u64* slots, u64 key) {
    #pragma unroll
    for (int s = 0; s < 8; s++) {
        u64 old = atomicMax(&slots[s], key);
        if (old < key) key = old;
        if (key == 0ull) break;
    }
}

// Rare path: push qualifying elements of one float4 into the shared top-8.
__device__ __noinline__ void push4(float4 v, float e8f, u64* slots,
                                   unsigned tid, unsigned* cnt) {
    float e[4] = {v.x, v.y, v.z, v.w};
    #pragma unroll
    for (int j = 0; j < 4; j++) {
        if (e[j] >= e8f) {
            u64 key = (((u64)__float_as_uint(e[j])) << 32)
                    | (u64)((tid << 16) | ((*cnt)++ & 0xffffu));
            if (key > ((volatile u64*)slots)[7]) cascade_insert(slots, key);
        }
    }
}

__global__ __launch_bounds__(NTHREADS) void robust_combiner_kernel(
    const int*   __restrict__ tgt_index,
    const float* __restrict__ knn_dists,
    const float* __restrict__ knn_key,
    const float* __restrict__ net_probs,
    const float* __restrict__ net_sel,
    const float* __restrict__ W_func, const float* __restrict__ b_func,
    const float* __restrict__ W1a,    const float* __restrict__ b1a,
    const float* __restrict__ W1b,    const float* __restrict__ b1b,
    const float* __restrict__ W2a,    const float* __restrict__ b2a,
    const float* __restrict__ W2b,    const float* __restrict__ b2b,
    float* __restrict__ out)
{
    const int cta = blockIdx.x;
    const int tid = threadIdx.x;

    __shared__ float4 s_buf[NBUF][CH_F4];          // 38400 B
    __shared__ float  s_W2a[32 * 64];              // 8192 B
    __shared__ u64    s_mbar[NBUF];
    __shared__ u64    s_seed[8];
    __shared__ u64    s_slots[8];
    __shared__ float  s_topv[8];
    __shared__ float  s_d[KNN], s_cnt[KNN], s_p[KNN];
    __shared__ int    s_tgt[KNN];

    #pragma unroll
    for (int j = 0; j < 8; j++) s_W2a[tid * 8 + j] = W2a[tid * 8 + j];
    if (tid < 8) { s_seed[tid] = 0ull; s_slots[tid] = 0ull; }

    uint32_t mb[NBUF], bufa[NBUF];
    #pragma unroll
    for (int b = 0; b < NBUF; b++) {
        mb[b]   = smem_u32(&s_mbar[b]);
        bufa[b] = smem_u32(&s_buf[b][0]);
    }

    // This CTA's contiguous 4-row region.
    const char* sreg = (const char*)net_probs + (size_t)cta * ROWS_PER_CTA * ROW_BYTES;
    float* oreg = out + (size_t)cta * ROWS_PER_CTA * VOCAB;
    const float4 z4 = make_float4(0.f, 0.f, 0.f, 0.f);

    if (tid == 0) {
        #pragma unroll
        for (int b = 0; b < NBUF; b++) mbar_init(mb[b], 1);
    }
    __syncthreads();
    if (tid == 0) {
        fence_proxy_async_cta();
        #pragma unroll
        for (int b = 0; b < NBUF; b++) {
            mbar_expect_tx(mb[b], CH_BYTES);
            bulk_g2s(bufa[b], sreg + b * CH_BYTES, CH_BYTES, mb[b]);
        }
    }

    unsigned pcnt = 0;

#define PROC4(v) do {                                                    \
        float _m = fmaxf(fmaxf((v).x, (v).y), fmaxf((v).z, (v).w));     \
        if (_m >= e8f) push4((v), e8f, s_slots, (unsigned)tid, &pcnt);   \
    } while (0)

    #pragma unroll 1
    for (int r = 0; r < ROWS_PER_CTA; r++) {
        const int t = cta * ROWS_PER_CTA + r;
        const int c0 = r * NCH_ROW;                // first chunk of this row
        float* orow = oreg + (size_t)r * VOCAB;

        // ---- Seed threshold from this row's first chunk ----
        {
            const int b = c0 % NBUF;
            mbar_wait(mb[b], (c0 / NBUF) & 1);
            float m = 0.0f;
            #pragma unroll
            for (int j = 0; j < 4; j++) {
                int i = j * NTHREADS + tid;
                if (i < CH_F4) {
                    float4 v = s_buf[b][i];
                    m = fmaxf(m, fmaxf(fmaxf(v.x, v.y), fmaxf(v.z, v.w)));
                }
            }
            float cand = m;
            #pragma unroll
            for (int rr = 0; rr < 8; rr++) {
                u64 key = (((u64)__float_as_uint(cand)) << 32) | (unsigned)tid;
                atomicMax(&s_seed[rr], key);
                __syncthreads();
                if ((unsigned)(s_seed[rr] & 0xffffffffull) == (unsigned)tid) cand = 0.0f;
            }
        }
        const float e8f = __uint_as_float((unsigned)(s_seed[7] >> 32));

        // ---- Consume this row's 10 chunks; ring keeps streaming ahead ----
        #pragma unroll 1
        for (int cc = 0; cc < NCH_ROW; cc++) {
            const int c = c0 + cc;
            const int b = c % NBUF;
            if (cc > 0) mbar_wait(mb[b], (c / NBUF) & 1);
            float4* od = (float4*)(orow + cc * CH_FLOATS);
            #pragma unroll
            for (int j = 0; j < 4; j++) {
                int i = j * NTHREADS + tid;
                if (i < CH_F4) {
                    float4 v = s_buf[b][i];
                    __stcs(&od[i], z4);
                    PROC4(v);
                }
            }
            __syncthreads();
            if (tid == 0 && c + NBUF < NCH_CTA) {
                mbar_expect_tx(mb[b], CH_BYTES);
                bulk_g2s(bufa[b], sreg + (size_t)(c + NBUF) * CH_BYTES, CH_BYTES, mb[b]);
            }
        }

        // ---- Finalize sorted top-8, reset state for next row ----
        if (tid == 0) {
            float tv[8];
            #pragma unroll
            for (int rr = 0; rr < 8; rr++) tv[rr] = __uint_as_float((unsigned)(s_slots[rr] >> 32));
            #pragma unroll
            for (int i = 1; i < 8; i++) {
                float x = tv[i]; int j = i - 1;
                while (j >= 0 && tv[j] < x) { tv[j + 1] = tv[j]; j--; }
                tv[j + 1] = x;
            }
            #pragma unroll
            for (int rr = 0; rr < 8; rr++) s_topv[rr] = tv[rr];
        }
        __syncthreads();
        if (tid < 8) { s_slots[tid] = 0ull; s_seed[tid] = 0ull; }
        __syncthreads();

        // ---- Scalar math on warp 0 (ring continues fetching next row) ----
        if (tid < KNN) {
            const int k = tid;
            const int base = t * KNN;
            const int   tg = tgt_index[base + k];
            const float d  = knn_dists[base + k];
            const float lk = logf(knn_key[base + k]);
            const float ls = logf(net_sel[base + k]);
            s_tgt[k] = tg;
            s_d[k]   = d;
            __syncwarp();

            // distinct-nonzero-label prefix counts
            int flag = (tg != 0) ? 1 : 0;
            for (int j = 0; j < k; j++)
                if (s_tgt[j] == tg) flag = 0;
            int c = flag;
            #pragma unroll
            for (int o = 1; o < 32; o <<= 1) {
                int v = __shfl_up_sync(0xffffffffu, c, o);
                if (k >= o) c += v;
            }
            s_cnt[k] = (float)c;
            __syncwarp();

            // noise_logit: Linear(2,4)-tanh-Linear(4,1)
            float noise = b1b[0];
            #pragma unroll
            for (int mm = 0; mm < 4; mm++) {
                float h = tanhf(W1a[2 * mm] * lk + W1a[2 * mm + 1] * ls + b1a[mm]);
                noise += W1b[mm] * h;
            }

            // sim_lambda: dot([log(top8), log_key, log_sel], W_func) + b
            float part = lk * W_func[8 + k] + ls * W_func[40 + k];
            if (k < 8) part += logf(s_topv[k]) * W_func[k];
            float sim = warp_sum(part) + b_func[0];

            // lambda_logit: Linear(64,32)-tanh-Linear(32,2); lane k = hidden unit k
            float acc = b2a[k];
            #pragma unroll 8
            for (int j = 0; j < 32; j++)
                acc += s_W2a[k * 64 + j] * s_d[j] + s_W2a[k * 64 + 32 + j] * s_cnt[j];
            float h2 = tanhf(acc);
            float l0 = warp_sum(W2b[k]      * h2) + b2b[0];
            float l1 = warp_sum(W2b[32 + k] * h2) + b2b[1];

            float lam   = 1.0f / (1.0f + expf(sim - l0));   // softmax([l0,sim])[0]
            float tempe = 1.0f / (1.0f + expf(-l1));

            // probs = softmax(-d * tempe + noise) over K
            float logit = -d * tempe + noise;
            float mx = warp_max(logit);
            float e  = expf(logit - mx);
            float ssum = warp_sum(e);
            s_p[k] = e / ssum;
            __syncwarp();

            // scatter (sequential, last-wins) into zeroed row + lambda
            if (k == 0) {
                #pragma unroll
                for (int j = 0; j < KNN; j++) orow[s_tgt[j]] = s_p[j];
                out[(size_t)TOKENS * VOCAB + t] = lam;
            }
        }
    }
#undef PROC4
}

extern "C" void kernel_launch(void* const* d_in, const int* in_sizes, int n_in,
                              void* d_out, int out_size) {
    const int*   tgt_index = (const int*)  d_in[0];
    const float* knn_dists = (const float*)d_in[1];
    const float* knn_key   = (const float*)d_in[2];
    const float* net_probs = (const float*)d_in[3];
    const float* net_sel   = (const float*)d_in[4];
    const float* W_func    = (const float*)d_in[5];
    const float* b_func    = (const float*)d_in[6];
    const float* W1a       = (const float*)d_in[7];
    const float* b1a       = (const float*)d_in[8];
    const float* W1b       = (const float*)d_in[9];
    const float* b1b       = (const float*)d_in[10];
    const float* W2a       = (const float*)d_in[11];
    const float* b2a       = (const float*)d_in[12];
    const float* W2b       = (const float*)d_in[13];
    const float* b2b       = (const float*)d_in[14];
    float* out = (float*)d_out;

    robust_combiner_kernel<<<NBLOCKS, NTHREADS>>>(
        tgt_index, knn_dists, knn_key, net_probs, net_sel,
        W_func, b_func, W1a, b1a, W1b, b1b, W2a, b2a, W2b, b2b, out);
}

// round 10
// speedup vs baseline: 1.1461x; 1.0939x over previous
#include <cuda_runtime.h>
#include <math.h>
#include <stdint.h>

#define KNN 32
#define VOCAB 32000
#define TOKENS 2048           // B*S = 4*512
#define NTHREADS 256
#define NV4 (VOCAB/4)         // 8000 float4 per row

typedef unsigned long long u64;

__device__ __forceinline__ void l2_prefetch_line(const void* p) {
    asm volatile("prefetch.global.L2 [%0];" :: "l"(p));
}

__device__ __forceinline__ float warp_sum(float v) {
    #pragma unroll
    for (int o = 16; o > 0; o >>= 1) v += __shfl_xor_sync(0xffffffffu, v, o);
    return v;
}
__device__ __forceinline__ float warp_max(float v) {
    #pragma unroll
    for (int o = 16; o > 0; o >>= 1) v = fmaxf(v, __shfl_xor_sync(0xffffffffu, v, o));
    return v;
}

// Lock-free sorted top-8 insert: cascading atomicMax. Displaced keys push down.
__device__ __forceinline__ void cascade_insert(u64* slots, u64 key) {
    #pragma unroll
    for (int s = 0; s < 8; s++) {
        u64 old = atomicMax(&slots[s], key);
        if (old < key) key = old;
        if (key == 0ull) break;
    }
}

// Rare path: push qualifying elements of one float4 into the shared top-8.
__device__ __noinline__ void push4(float4 v, float e8f, u64* slots,
                                   unsigned tid, unsigned* cnt) {
    float e[4] = {v.x, v.y, v.z, v.w};
    #pragma unroll
    for (int j = 0; j < 4; j++) {
        if (e[j] >= e8f) {
            u64 key = (((u64)__float_as_uint(e[j])) << 32)
                    | (u64)((tid << 16) | ((*cnt)++ & 0xffffu));
            if (key > ((volatile u64*)slots)[7]) cascade_insert(slots, key);
        }
    }
}

__global__ __launch_bounds__(NTHREADS) void robust_combiner_kernel(
    const int*   __restrict__ tgt_index,
    const float* __restrict__ knn_dists,
    const float* __restrict__ knn_key,
    const float* __restrict__ net_probs,
    const float* __restrict__ net_sel,
    const float* __restrict__ W_func, const float* __restrict__ b_func,
    const float* __restrict__ W1a,    const float* __restrict__ b1a,
    const float* __restrict__ W1b,    const float* __restrict__ b1b,
    const float* __restrict__ W2a,    const float* __restrict__ b2a,
    const float* __restrict__ W2b,    const float* __restrict__ b2b,
    float* __restrict__ out)
{
    const int t   = blockIdx.x;
    const int tid = threadIdx.x;

    __shared__ float s_W2a[32 * 64];
    __shared__ u64   s_seed[8];
    __shared__ u64   s_slots[8];
    __shared__ float s_topv[8];
    __shared__ float s_d[KNN], s_cnt[KNN], s_p[KNN];
    __shared__ int   s_tgt[KNN];

    const float4* __restrict__ src = (const float4*)(net_probs + (size_t)t * VOCAB);
    float4*       __restrict__ dst = (float4*)(out + (size_t)t * VOCAB);
    const float4 z4 = make_float4(0.f, 0.f, 0.f, 0.f);

    // ---- Front-load L2 prefetch of this CTA's whole input row.
    // 1000 x 128B lines; thread i prefetches lines i, i+256, i+512, i+744(768 partial).
    {
        const char* rb = (const char*)src;
        l2_prefetch_line(rb + (size_t)tid * 128);
        l2_prefetch_line(rb + (size_t)(tid + 256) * 128);
        l2_prefetch_line(rb + (size_t)(tid + 512) * 128);
        if (tid < 232) l2_prefetch_line(rb + (size_t)(tid + 768) * 128);
    }

    // stage W2a into shared (2048 floats, 8 per thread)
    #pragma unroll
    for (int j = 0; j < 8; j++) s_W2a[tid * 8 + j] = W2a[tid * 8 + j];
    if (tid < 8) { s_seed[tid] = 0ull; s_slots[tid] = 0ull; }

    // -------- Phase 0: stride 0 + seed threshold e8 (8th largest of 256 max4s) --------
    float4 v0 = __ldcs(&src[tid]);
    __stcs(&dst[tid], z4);
    float max0 = fmaxf(fmaxf(v0.x, v0.y), fmaxf(v0.z, v0.w));
    __syncthreads();

    {
        float cand = max0;
        #pragma unroll
        for (int r = 0; r < 8; r++) {
            u64 key = (((u64)__float_as_uint(cand)) << 32) | (unsigned)tid;
            atomicMax(&s_seed[r], key);
            __syncthreads();
            if ((unsigned)(s_seed[r] & 0xffffffffull) == (unsigned)tid) cand = 0.0f;
        }
    }
    const float e8f = __uint_as_float((unsigned)(s_seed[7] >> 32));

    unsigned pcnt = 0;
    push4(v0, e8f, s_slots, (unsigned)tid, &pcnt);   // stride-0 elements into slots

    // -------- Phase 1: hot stream loop, strides 1..30 + partial stride 31 --------
#define PROC4(v) do {                                                    \
        float _m = fmaxf(fmaxf((v).x, (v).y), fmaxf((v).z, (v).w));     \
        if (_m >= e8f) push4((v), e8f, s_slots, (unsigned)tid, &pcnt);   \
    } while (0)

    {
        int i = tid + NTHREADS;                 // stride 1
        #pragma unroll 1
        for (int g = 0; g < 7; g++) {           // strides 1..28
            float4 a = __ldcs(&src[i]);
            float4 b = __ldcs(&src[i +     NTHREADS]);
            float4 c = __ldcs(&src[i + 2 * NTHREADS]);
            float4 d = __ldcs(&src[i + 3 * NTHREADS]);
            __stcs(&dst[i],                z4);
            __stcs(&dst[i +     NTHREADS], z4);
            __stcs(&dst[i + 2 * NTHREADS], z4);
            __stcs(&dst[i + 3 * NTHREADS], z4);
            PROC4(a); PROC4(b); PROC4(c); PROC4(d);
            i += 4 * NTHREADS;
        }
        // strides 29, 30
        {
            float4 a = __ldcs(&src[i]);
            float4 b = __ldcs(&src[i + NTHREADS]);
            __stcs(&dst[i],            z4);
            __stcs(&dst[i + NTHREADS], z4);
            PROC4(a); PROC4(b);
            i += 2 * NTHREADS;
        }
        // stride 31: 64 lanes
        if (i < NV4) {
            float4 a = __ldcs(&src[i]);
            __stcs(&dst[i], z4);
            PROC4(a);
        }
    }
#undef PROC4
    __syncthreads();

    // -------- Phase 2: finalize sorted top-8 values --------
    if (tid == 0) {
        float tv[8];
        #pragma unroll
        for (int r = 0; r < 8; r++) tv[r] = __uint_as_float((unsigned)(s_slots[r] >> 32));
        #pragma unroll
        for (int i = 1; i < 8; i++) {           // insertion sort, descending
            float x = tv[i]; int j = i - 1;
            while (j >= 0 && tv[j] < x) { tv[j + 1] = tv[j]; j--; }
            tv[j + 1] = x;
        }
        #pragma unroll
        for (int r = 0; r < 8; r++) s_topv[r] = tv[r];
    }
    __syncthreads();

    // -------- Phase 3: scalar math on warp 0 --------
    if (tid < KNN) {
        const int k = tid;
        const int base = t * KNN;
        const int   tg = tgt_index[base + k];
        const float d  = knn_dists[base + k];
        const float lk = logf(knn_key[base + k]);
        const float ls = logf(net_sel[base + k]);
        s_tgt[k] = tg;
        s_d[k]   = d;
        __syncwarp();

        // distinct-nonzero-label prefix counts
        int flag = (tg != 0) ? 1 : 0;
        for (int j = 0; j < k; j++)
            if (s_tgt[j] == tg) flag = 0;
        int c = flag;
        #pragma unroll
        for (int o = 1; o < 32; o <<= 1) {
            int v = __shfl_up_sync(0xffffffffu, c, o);
            if (k >= o) c += v;
        }
        s_cnt[k] = (float)c;
        __syncwarp();

        // noise_logit: Linear(2,4)-tanh-Linear(4,1)
        float noise = b1b[0];
        #pragma unroll
        for (int m = 0; m < 4; m++) {
            float h = tanhf(W1a[2 * m] * lk + W1a[2 * m + 1] * ls + b1a[m]);
            noise += W1b[m] * h;
        }

        // sim_lambda: dot([log(top8), log_key, log_sel], W_func) + b
        float part = lk * W_func[8 + k] + ls * W_func[40 + k];
        if (k < 8) part += logf(s_topv[k]) * W_func[k];
        float sim = warp_sum(part) + b_func[0];

        // lambda_logit: Linear(64,32)-tanh-Linear(32,2); lane k = hidden unit k
        float acc = b2a[k];
        #pragma unroll 8
        for (int j = 0; j < 32; j++)
            acc += s_W2a[k * 64 + j] * s_d[j] + s_W2a[k * 64 + 32 + j] * s_cnt[j];
        float h2 = tanhf(acc);
        float l0 = warp_sum(W2b[k]      * h2) + b2b[0];
        float l1 = warp_sum(W2b[32 + k] * h2) + b2b[1];

        // knn_lambda = softmax([l0, sim])[0] = sigmoid(l0 - sim)
        float lam   = 1.0f / (1.0f + expf(sim - l0));
        float tempe = 1.0f / (1.0f + expf(-l1));

        // probs = softmax(-d * tempe + noise) over K
        float logit = -d * tempe + noise;
        float mx = warp_max(logit);
        float e  = expf(logit - mx);
        float ssum = warp_sum(e);
        s_p[k] = e / ssum;
        __syncwarp();

        // -------- Phase 4: scatter (sequential, last-wins) + lambda --------
        if (k == 0) {
            float* row = out + (size_t)t * VOCAB;
            #pragma unroll
            for (int j = 0; j < KNN; j++) row[s_tgt[j]] = s_p[j];
            out[(size_t)TOKENS * VOCAB + t] = lam;
        }
    }
}

extern "C" void kernel_launch(void* const* d_in, const int* in_sizes, int n_in,
                              void* d_out, int out_size) {
    const int*   tgt_index = (const int*)  d_in[0];
    const float* knn_dists = (const float*)d_in[1];
    const float* knn_key   = (const float*)d_in[2];
    const float* net_probs = (const float*)d_in[3];
    const float* net_sel   = (const float*)d_in[4];
    const float* W_func    = (const float*)d_in[5];
    const float* b_func    = (const float*)d_in[6];
    const float* W1a       = (const float*)d_in[7];
    const float* b1a       = (const float*)d_in[8];
    const float* W1b       = (const float*)d_in[9];
    const float* b1b       = (const float*)d_in[10];
    const float* W2a       = (const float*)d_in[11];
    const float* b2a       = (const float*)d_in[12];
    const float* W2b       = (const float*)d_in[13];
    const float* b2b       = (const float*)d_in[14];
    float* out = (float*)d_out;

    robust_combiner_kernel<<<TOKENS, NTHREADS>>>(
        tgt_index, knn_dists, knn_key, net_probs, net_sel,
        W_func, b_func, W1a, b1a, W1b, b1b, W2a, b2a, W2b, b2b, out);
}

// round 11
// speedup vs baseline: 1.2342x; 1.0769x over previous
#include <cuda_runtime.h>
#include <math.h>
#include <stdint.h>

#define KNN 32
#define VOCAB 32000
#define TOKENS 2048           // B*S = 4*512
#define NTHREADS 256
#define NV4 (VOCAB/4)         // 8000 float4 per row

typedef unsigned long long u64;

__device__ __forceinline__ void l2_prefetch_line(const void* p) {
    asm volatile("prefetch.global.L2 [%0];" :: "l"(p));
}

__device__ __forceinline__ float warp_sum(float v) {
    #pragma unroll
    for (int o = 16; o > 0; o >>= 1) v += __shfl_xor_sync(0xffffffffu, v, o);
    return v;
}
__device__ __forceinline__ float warp_max(float v) {
    #pragma unroll
    for (int o = 16; o > 0; o >>= 1) v = fmaxf(v, __shfl_xor_sync(0xffffffffu, v, o));
    return v;
}

// Lock-free sorted top-8 insert: cascading atomicMax. Displaced keys push down.
__device__ __forceinline__ void cascade_insert(u64* slots, u64 key) {
    #pragma unroll
    for (int s = 0; s < 8; s++) {
        u64 old = atomicMax(&slots[s], key);
        if (old < key) key = old;
        if (key == 0ull) break;
    }
}

// Rare path: push qualifying elements of one float4 into the shared top-8.
__device__ __noinline__ void push4(float4 v, float e8f, u64* slots,
                                   unsigned tid, unsigned* cnt) {
    float e[4] = {v.x, v.y, v.z, v.w};
    #pragma unroll
    for (int j = 0; j < 4; j++) {
        if (e[j] >= e8f) {
            u64 key = (((u64)__float_as_uint(e[j])) << 32)
                    | (u64)((tid << 16) | ((*cnt)++ & 0xffffu));
            if (key > ((volatile u64*)slots)[7]) cascade_insert(slots, key);
        }
    }
}

__global__ __launch_bounds__(NTHREADS, 8) void robust_combiner_kernel(
    const int*   __restrict__ tgt_index,
    const float* __restrict__ knn_dists,
    const float* __restrict__ knn_key,
    const float* __restrict__ net_probs,
    const float* __restrict__ net_sel,
    const float* __restrict__ W_func, const float* __restrict__ b_func,
    const float* __restrict__ W1a,    const float* __restrict__ b1a,
    const float* __restrict__ W1b,    const float* __restrict__ b1b,
    const float* __restrict__ W2a,    const float* __restrict__ b2a,
    const float* __restrict__ W2b,    const float* __restrict__ b2b,
    float* __restrict__ out)
{
    const int t   = blockIdx.x;
    const int tid = threadIdx.x;

    __shared__ float s_W2a[32 * 64];
    __shared__ u64   s_seed[8];
    __shared__ u64   s_slots[8];
    __shared__ float s_topv[8];
    __shared__ float s_d[KNN], s_cnt[KNN], s_p[KNN];
    __shared__ int   s_tgt[KNN];

    const float4* __restrict__ src = (const float4*)(net_probs + (size_t)t * VOCAB);
    float4*       __restrict__ dst = (float4*)(out + (size_t)t * VOCAB);
    const float4 z4 = make_float4(0.f, 0.f, 0.f, 0.f);

    // ---- Front-load L2 prefetch of this CTA's whole input row.
    // 1000 x 128B lines; thread i prefetches lines i, i+256, i+512, i+744(768 partial).
    {
        const char* rb = (const char*)src;
        l2_prefetch_line(rb + (size_t)tid * 128);
        l2_prefetch_line(rb + (size_t)(tid + 256) * 128);
        l2_prefetch_line(rb + (size_t)(tid + 512) * 128);
        if (tid < 232) l2_prefetch_line(rb + (size_t)(tid + 768) * 128);
    }

    // stage W2a into shared (2048 floats, 8 per thread)
    #pragma unroll
    for (int j = 0; j < 8; j++) s_W2a[tid * 8 + j] = W2a[tid * 8 + j];
    if (tid < 8) { s_seed[tid] = 0ull; s_slots[tid] = 0ull; }

    // -------- Phase 0: stride 0 + seed threshold e8 (8th largest of 256 max4s) --------
    float4 v0 = __ldcs(&src[tid]);
    __stcs(&dst[tid], z4);
    float max0 = fmaxf(fmaxf(v0.x, v0.y), fmaxf(v0.z, v0.w));
    __syncthreads();

    {
        float cand = max0;
        #pragma unroll
        for (int r = 0; r < 8; r++) {
            u64 key = (((u64)__float_as_uint(cand)) << 32) | (unsigned)tid;
            atomicMax(&s_seed[r], key);
            __syncthreads();
            if ((unsigned)(s_seed[r] & 0xffffffffull) == (unsigned)tid) cand = 0.0f;
        }
    }
    const float e8f = __uint_as_float((unsigned)(s_seed[7] >> 32));

    unsigned pcnt = 0;
    push4(v0, e8f, s_slots, (unsigned)tid, &pcnt);   // stride-0 elements into slots

    // -------- Phase 1: hot stream loop, strides 1..30 + partial stride 31 --------
#define PROC4(v) do {                                                    \
        float _m = fmaxf(fmaxf((v).x, (v).y), fmaxf((v).z, (v).w));     \
        if (_m >= e8f) push4((v), e8f, s_slots, (unsigned)tid, &pcnt);   \
    } while (0)

    {
        int i = tid + NTHREADS;                 // stride 1
        #pragma unroll 1
        for (int g = 0; g < 7; g++) {           // strides 1..28
            float4 a = __ldcs(&src[i]);
            float4 b = __ldcs(&src[i +     NTHREADS]);
            float4 c = __ldcs(&src[i + 2 * NTHREADS]);
            float4 d = __ldcs(&src[i + 3 * NTHREADS]);
            __stcs(&dst[i],                z4);
            __stcs(&dst[i +     NTHREADS], z4);
            __stcs(&dst[i + 2 * NTHREADS], z4);
            __stcs(&dst[i + 3 * NTHREADS], z4);
            PROC4(a); PROC4(b); PROC4(c); PROC4(d);
            i += 4 * NTHREADS;
        }
        // strides 29, 30
        {
            float4 a = __ldcs(&src[i]);
            float4 b = __ldcs(&src[i + NTHREADS]);
            __stcs(&dst[i],            z4);
            __stcs(&dst[i + NTHREADS], z4);
            PROC4(a); PROC4(b);
            i += 2 * NTHREADS;
        }
        // stride 31: 64 lanes
        if (i < NV4) {
            float4 a = __ldcs(&src[i]);
            __stcs(&dst[i], z4);
            PROC4(a);
        }
    }
#undef PROC4
    __syncthreads();

    // -------- Phase 2: finalize sorted top-8 values --------
    if (tid == 0) {
        float tv[8];
        #pragma unroll
        for (int r = 0; r < 8; r++) tv[r] = __uint_as_float((unsigned)(s_slots[r] >> 32));
        #pragma unroll
        for (int i = 1; i < 8; i++) {           // insertion sort, descending
            float x = tv[i]; int j = i - 1;
            while (j >= 0 && tv[j] < x) { tv[j + 1] = tv[j]; j--; }
            tv[j + 1] = x;
        }
        #pragma unroll
        for (int r = 0; r < 8; r++) s_topv[r] = tv[r];
    }
    __syncthreads();

    // -------- Phase 3: scalar math on warp 0 --------
    if (tid < KNN) {
        const int k = tid;
        const int base = t * KNN;
        const int   tg = tgt_index[base + k];
        const float d  = knn_dists[base + k];
        const float lk = logf(knn_key[base + k]);
        const float ls = logf(net_sel[base + k]);
        s_tgt[k] = tg;
        s_d[k]   = d;
        __syncwarp();

        // distinct-nonzero-label prefix counts
        int flag = (tg != 0) ? 1 : 0;
        for (int j = 0; j < k; j++)
            if (s_tgt[j] == tg) flag = 0;
        int c = flag;
        #pragma unroll
        for (int o = 1; o < 32; o <<= 1) {
            int v = __shfl_up_sync(0xffffffffu, c, o);
            if (k >= o) c += v;
        }
        s_cnt[k] = (float)c;
        __syncwarp();

        // noise_logit: Linear(2,4)-tanh-Linear(4,1)
        float noise = b1b[0];
        #pragma unroll
        for (int m = 0; m < 4; m++) {
            float h = tanhf(W1a[2 * m] * lk + W1a[2 * m + 1] * ls + b1a[m]);
            noise += W1b[m] * h;
        }

        // sim_lambda: dot([log(top8), log_key, log_sel], W_func) + b
        float part = lk * W_func[8 + k] + ls * W_func[40 + k];
        if (k < 8) part += logf(s_topv[k]) * W_func[k];
        float sim = warp_sum(part) + b_func[0];

        // lambda_logit: Linear(64,32)-tanh-Linear(32,2); lane k = hidden unit k
        float acc = b2a[k];
        #pragma unroll 8
        for (int j = 0; j < 32; j++)
            acc += s_W2a[k * 64 + j] * s_d[j] + s_W2a[k * 64 + 32 + j] * s_cnt[j];
        float h2 = tanhf(acc);
        float l0 = warp_sum(W2b[k]      * h2) + b2b[0];
        float l1 = warp_sum(W2b[32 + k] * h2) + b2b[1];

        // knn_lambda = softmax([l0, sim])[0] = sigmoid(l0 - sim)
        float lam   = 1.0f / (1.0f + expf(sim - l0));
        float tempe = 1.0f / (1.0f + expf(-l1));

        // probs = softmax(-d * tempe + noise) over K
        float logit = -d * tempe + noise;
        float mx = warp_max(logit);
        float e  = expf(logit - mx);
        float ssum = warp_sum(e);
        s_p[k] = e / ssum;
        __syncwarp();

        // -------- Phase 4: scatter (sequential, last-wins) + lambda --------
        if (k == 0) {
            float* row = out + (size_t)t * VOCAB;
            #pragma unroll
            for (int j = 0; j < KNN; j++) row[s_tgt[j]] = s_p[j];
            out[(size_t)TOKENS * VOCAB + t] = lam;
        }
    }
}

extern "C" void kernel_launch(void* const* d_in, const int* in_sizes, int n_in,
                              void* d_out, int out_size) {
    const int*   tgt_index = (const int*)  d_in[0];
    const float* knn_dists = (const float*)d_in[1];
    const float* knn_key   = (const float*)d_in[2];
    const float* net_probs = (const float*)d_in[3];
    const float* net_sel   = (const float*)d_in[4];
    const float* W_func    = (const float*)d_in[5];
    const float* b_func    = (const float*)d_in[6];
    const float* W1a       = (const float*)d_in[7];
    const float* b1a       = (const float*)d_in[8];
    const float* W1b       = (const float*)d_in[9];
    const float* b1b       = (const float*)d_in[10];
    const float* W2a       = (const float*)d_in[11];
    const float* b2a       = (const float*)d_in[12];
    const float* W2b       = (const float*)d_in[13];
    const float* b2b       = (const float*)d_in[14];
    float* out = (float*)d_out;

    robust_combiner_kernel<<<TOKENS, NTHREADS>>>(
        tgt_index, knn_dists, knn_key, net_probs, net_sel,
        W_func, b_func, W1a, b1a, W1b, b1b, W2a, b2a, W2b, b2b, out);
}